// round 3
// baseline (speedup 1.0000x reference)
#include <cuda_runtime.h>
#include <cstdint>

// SDF_75806172774865 — smem-staged, double-buffered cp.async version.
// points: (N,P,3) f32; v,vn: (N,P,K,3) f32; sr: (N,P,K) f32; out: (N,) f32
//
// Fast path (K==60, total_pts%16==0):
//   Tiles of 16 points. Stage v/vn/sr for a tile into shared memory with
//   fully-coalesced float4 cp.async (minimum L1tex wavefronts: 1 per 128B
//   line, vs 3x replay with the previous 12B-stride scalar LDGs).
//   Double-buffered: prefetch tile i+1 while computing tile i.
//   Compute: warp w handles point w of the tile; lanes stride over k
//   (smem reads, stride-3 floats -> bank-conflict-free).

#define THREADS 512
#define WARPS 16
#define TILE_PTS 16
#define KFIX 60
#define V_F4_PER_TILE  (TILE_PTS * 45)   // 720 float4 (= 16 pts * 180 floats)
#define SR_F4_PER_TILE (TILE_PTS * 15)   // 240 float4 (= 16 pts * 60 floats)
#define BUF_F4 (2 * V_F4_PER_TILE + SR_F4_PER_TILE)  // 1680 float4 per buffer
#define SMEM_BYTES (2 * BUF_F4 * 16)                 // 53760 B

__global__ void sdf_init_out(float* out, int n) {
    int i = threadIdx.x;
    if (i < n) out[i] = 0.0f;
}

__device__ __forceinline__ void cpa16(float4* smem_dst, const float4* gsrc) {
    uint32_t s = (uint32_t)__cvta_generic_to_shared(smem_dst);
    asm volatile("cp.async.cg.shared.global [%0], [%1], 16;\n"
                 :: "r"(s), "l"(gsrc));
}
__device__ __forceinline__ void cpa_commit() {
    asm volatile("cp.async.commit_group;" ::: "memory");
}
template <int N>
__device__ __forceinline__ void cpa_wait() {
    asm volatile("cp.async.wait_group %0;" :: "n"(N) : "memory");
}

__device__ __forceinline__ void stage_tile(const float4* __restrict__ gv,
                                           const float4* __restrict__ gvn,
                                           const float4* __restrict__ gsr,
                                           int tile, float4* sbuf, int tid) {
    const float4* src_v  = gv  + (size_t)tile * V_F4_PER_TILE;
    const float4* src_vn = gvn + (size_t)tile * V_F4_PER_TILE;
    const float4* src_sr = gsr + (size_t)tile * SR_F4_PER_TILE;
    float4* dv  = sbuf;
    float4* dvn = sbuf + V_F4_PER_TILE;
    float4* dsr = sbuf + 2 * V_F4_PER_TILE;
    #pragma unroll 2
    for (int i = tid; i < V_F4_PER_TILE; i += THREADS) cpa16(dv + i,  src_v + i);
    #pragma unroll 2
    for (int i = tid; i < V_F4_PER_TILE; i += THREADS) cpa16(dvn + i, src_vn + i);
    for (int i = tid; i < SR_F4_PER_TILE; i += THREADS) cpa16(dsr + i, src_sr + i);
}

__global__ __launch_bounds__(THREADS)
void sdf_kernel_fast(const float* __restrict__ points,
                     const float4* __restrict__ v4,
                     const float4* __restrict__ vn4,
                     const float4* __restrict__ sr4,
                     float* __restrict__ out,
                     int ntiles, int P)
{
    extern __shared__ float4 smem[];
    __shared__ float s_acc[2];

    const int tid  = threadIdx.x;
    const int warp = tid >> 5;
    const int lane = tid & 31;
    if (tid < 2) s_acc[tid] = 0.0f;
    __syncthreads();

    const int stride = gridDim.x;
    const int t0 = blockIdx.x;

    if (t0 < ntiles) {
        stage_tile(v4, vn4, sr4, t0, smem, tid);
        cpa_commit();
    }

    int bufi = 0;
    for (int t = t0; t < ntiles; t += stride) {
        const int tn = t + stride;
        const bool have_next = tn < ntiles;
        if (have_next) {
            stage_tile(v4, vn4, sr4, tn, smem + (bufi ^ 1) * BUF_F4, tid);
            cpa_commit();
            cpa_wait<1>();   // current tile's group complete, next may be in flight
        } else {
            cpa_wait<0>();
        }
        __syncthreads();

        // ---- compute: warp 'warp' handles point t*16 + warp ----
        const int pt = t * TILE_PTS + warp;
        const float* base = (const float*)(smem + bufi * BUF_F4);
        const float* sv   = base + warp * 180;
        const float* svn  = base + V_F4_PER_TILE * 4 + warp * 180;
        const float* ssr  = base + 2 * V_F4_PER_TILE * 4 + warp * 60;

        const float* pp = points + (size_t)pt * 3;
        const float px = pp[0];
        const float py = pp[1];
        const float pz = pp[2];

        float num = 0.0f;
        float den = 0.0f;

        // trip 0: k = lane (all 32 lanes)
        {
            const int b = lane * 3;
            const float dx = px - sv[b + 0];
            const float dy = py - sv[b + 1];
            const float dz = pz - sv[b + 2];
            const float d  = dx * dx + dy * dy + dz * dz;
            const float r  = ssr[lane];
            const float w  = 1.0f - d / r;
            const float w2 = w * w;
            const float phi = (d < r) ? (w2 * w2) : 1e-18f;
            const float dot = svn[b + 0] * dx + svn[b + 1] * dy + svn[b + 2] * dz;
            num = fmaf(phi, dot, num);
            den += phi;
        }
        // trip 1: k = lane + 32 (lanes < 28)
        if (lane + 32 < KFIX) {
            const int b = (lane + 32) * 3;
            const float dx = px - sv[b + 0];
            const float dy = py - sv[b + 1];
            const float dz = pz - sv[b + 2];
            const float d  = dx * dx + dy * dy + dz * dz;
            const float r  = ssr[lane + 32];
            const float w  = 1.0f - d / r;
            const float w2 = w * w;
            const float phi = (d < r) ? (w2 * w2) : 1e-18f;
            const float dot = svn[b + 0] * dx + svn[b + 1] * dy + svn[b + 2] * dz;
            num = fmaf(phi, dot, num);
            den += phi;
        }

        #pragma unroll
        for (int off = 16; off > 0; off >>= 1) {
            num += __shfl_xor_sync(0xffffffffu, num, off);
            den += __shfl_xor_sync(0xffffffffu, den, off);
        }

        if (lane == 0) {
            const float sdf = num / den;
            atomicAdd(&s_acc[pt / P], sdf * sdf);
        }
        __syncthreads();   // everyone done reading bufi before it is restaged
        bufi ^= 1;
    }

    __syncthreads();
    if (tid < 2) {
        const float val = s_acc[tid];
        if (val != 0.0f) atomicAdd(&out[tid], val);
    }
}

// ---- generic fallback (any K / shape), same as R2 kernel ----
#define FB_WARPS 16
__global__ __launch_bounds__(FB_WARPS * 32)
void sdf_kernel_generic(const float* __restrict__ points,
                        const float* __restrict__ v,
                        const float* __restrict__ vn,
                        const float* __restrict__ sr,
                        float* __restrict__ out,
                        int total_pts, int P, int K)
{
    __shared__ float s_acc[2];
    const int tid  = threadIdx.x;
    if (tid < 2) s_acc[tid] = 0.0f;
    __syncthreads();

    const int warp = tid >> 5;
    const int lane = tid & 31;
    const int pt   = blockIdx.x * FB_WARPS + warp;

    if (pt < total_pts) {
        const float* pp = points + (size_t)pt * 3;
        const float px = pp[0], py = pp[1], pz = pp[2];
        const float* vb  = v  + (size_t)pt * K * 3;
        const float* vnb = vn + (size_t)pt * K * 3;
        const float* srb = sr + (size_t)pt * K;

        float num = 0.0f, den = 0.0f;
        for (int k = lane; k < K; k += 32) {
            const int b = k * 3;
            const float dx = px - vb[b + 0];
            const float dy = py - vb[b + 1];
            const float dz = pz - vb[b + 2];
            const float d  = dx * dx + dy * dy + dz * dz;
            const float r  = srb[k];
            const float w  = 1.0f - d / r;
            const float w2 = w * w;
            const float phi = (d < r) ? (w2 * w2) : 1e-18f;
            const float dot = vnb[b + 0] * dx + vnb[b + 1] * dy + vnb[b + 2] * dz;
            num = fmaf(phi, dot, num);
            den += phi;
        }
        #pragma unroll
        for (int off = 16; off > 0; off >>= 1) {
            num += __shfl_xor_sync(0xffffffffu, num, off);
            den += __shfl_xor_sync(0xffffffffu, den, off);
        }
        if (lane == 0) {
            const float sdf = num / den;
            atomicAdd(&s_acc[pt / P], sdf * sdf);
        }
    }
    __syncthreads();
    if (tid < 2) {
        const float val = s_acc[tid];
        if (val != 0.0f) atomicAdd(&out[tid], val);
    }
}

extern "C" void kernel_launch(void* const* d_in, const int* in_sizes, int n_in,
                              void* d_out, int out_size)
{
    const float* points = (const float*)d_in[0];
    const float* v      = (const float*)d_in[1];
    const float* vn     = (const float*)d_in[2];
    const float* sr     = (const float*)d_in[3];
    float* out          = (float*)d_out;

    const int total_pts = in_sizes[0] / 3;          // N*P
    const int N         = out_size;                 // 2
    const int P         = total_pts / N;            // 100000
    const int K         = in_sizes[3] / total_pts;  // 60

    sdf_init_out<<<1, 32>>>(out, N);

    if (K == KFIX && (total_pts % TILE_PTS) == 0) {
        static bool attr_set = false;
        if (!attr_set) {
            cudaFuncSetAttribute(sdf_kernel_fast,
                                 cudaFuncAttributeMaxDynamicSharedMemorySize,
                                 SMEM_BYTES);
            attr_set = true;
        }
        const int ntiles = total_pts / TILE_PTS;    // 12500
        int blocks = 148 * 4;                       // one full wave at 4 blocks/SM
        if (blocks > ntiles) blocks = ntiles;
        sdf_kernel_fast<<<blocks, THREADS, SMEM_BYTES>>>(
            points, (const float4*)v, (const float4*)vn, (const float4*)sr,
            out, ntiles, P);
    } else {
        const int blocks = (total_pts + FB_WARPS - 1) / FB_WARPS;
        sdf_kernel_generic<<<blocks, FB_WARPS * 32>>>(points, v, vn, sr, out,
                                                      total_pts, P, K);
    }
}

// round 4
// speedup vs baseline: 1.5254x; 1.5254x over previous
#include <cuda_runtime.h>

// SDF_75806172774865 — direct-load (R2 lineage), 2 points per warp, fast-div.
// points: (N,P,3) f32; v,vn: (N,P,K,3) f32; sr: (N,P,K) f32; out: (N,) f32
//
// Warp handles points {2w, 2w+1}; lanes stride over k. Interleaving two
// points doubles the front-batched LDG count per warp (28 loads in flight)
// and halves the per-point reduction/atomic/loop overhead. __fdividef
// replaces IEEE div (MUFU.RCP + MUL). K=60 specialized at compile time so
// both k-trips fully unroll.

#define WARPS_PER_BLOCK 16
#define THREADS_PER_BLOCK (WARPS_PER_BLOCK * 32)

__global__ void sdf_init_out(float* out, int n) {
    int i = threadIdx.x;
    if (i < n) out[i] = 0.0f;
}

template <int KT>
__global__ __launch_bounds__(THREADS_PER_BLOCK)
void sdf_kernel2(const float* __restrict__ points,
                 const float* __restrict__ v,
                 const float* __restrict__ vn,
                 const float* __restrict__ sr,
                 float* __restrict__ out,
                 int total_pts,   // N*P
                 int P,
                 int Krt)
{
    const int K = (KT > 0) ? KT : Krt;

    __shared__ float s_acc[2];
    const int tid  = threadIdx.x;
    if (tid < 2) s_acc[tid] = 0.0f;
    __syncthreads();

    const int warp = tid >> 5;
    const int lane = tid & 31;
    const int ptA  = (blockIdx.x * WARPS_PER_BLOCK + warp) * 2;
    const int ptB  = ptA + 1;
    const bool hasB = ptB < total_pts;

    if (ptA < total_pts) {
        const float* ppA = points + (size_t)ptA * 3;
        const float pxA = ppA[0], pyA = ppA[1], pzA = ppA[2];
        const float* vA  = v  + (size_t)ptA * K * 3;
        const float* vnA = vn + (size_t)ptA * K * 3;
        const float* srA = sr + (size_t)ptA * K;

        // B pointers: clamp to A when absent so loads stay in-bounds
        const int ptBc = hasB ? ptB : ptA;
        const float* ppB = points + (size_t)ptBc * 3;
        const float pxB = ppB[0], pyB = ppB[1], pzB = ppB[2];
        const float* vB  = v  + (size_t)ptBc * K * 3;
        const float* vnB = vn + (size_t)ptBc * K * 3;
        const float* srB = sr + (size_t)ptBc * K;

        float numA = 0.0f, denA = 0.0f;
        float numB = 0.0f, denB = 0.0f;

        #pragma unroll
        for (int k = lane; k < K; k += 32) {
            const int b = k * 3;
            // ---- issue all 14 loads up front ----
            const float avx = vA[b + 0],  avy = vA[b + 1],  avz = vA[b + 2];
            const float anx = vnA[b + 0], any_ = vnA[b + 1], anz = vnA[b + 2];
            const float ra  = srA[k];
            const float bvx = vB[b + 0],  bvy = vB[b + 1],  bvz = vB[b + 2];
            const float bnx = vnB[b + 0], bny = vnB[b + 1], bnz = vnB[b + 2];
            const float rb  = srB[k];

            // ---- point A ----
            {
                const float dx = pxA - avx, dy = pyA - avy, dz = pzA - avz;
                const float d  = dx * dx + dy * dy + dz * dz;
                const float w  = 1.0f - __fdividef(d, ra);
                const float w2 = w * w;
                const float phi = (d < ra) ? (w2 * w2) : 1e-18f;
                const float dot = anx * dx + any_ * dy + anz * dz;
                numA = fmaf(phi, dot, numA);
                denA += phi;
            }
            // ---- point B ----
            {
                const float dx = pxB - bvx, dy = pyB - bvy, dz = pzB - bvz;
                const float d  = dx * dx + dy * dy + dz * dz;
                const float w  = 1.0f - __fdividef(d, rb);
                const float w2 = w * w;
                const float phi = (d < rb) ? (w2 * w2) : 1e-18f;
                const float dot = bnx * dx + bny * dy + bnz * dz;
                numB = fmaf(phi, dot, numB);
                denB += phi;
            }
        }

        #pragma unroll
        for (int off = 16; off > 0; off >>= 1) {
            numA += __shfl_xor_sync(0xffffffffu, numA, off);
            denA += __shfl_xor_sync(0xffffffffu, denA, off);
            numB += __shfl_xor_sync(0xffffffffu, numB, off);
            denB += __shfl_xor_sync(0xffffffffu, denB, off);
        }

        if (lane == 0) {
            const float sdfA = __fdividef(numA, denA);
            float acc = sdfA * sdfA;
            if (hasB && (ptB / P) == (ptA / P)) {
                const float sdfB = __fdividef(numB, denB);
                acc += sdfB * sdfB;
                atomicAdd(&s_acc[ptA / P], acc);
            } else {
                atomicAdd(&s_acc[ptA / P], acc);
                if (hasB) {
                    const float sdfB = __fdividef(numB, denB);
                    atomicAdd(&s_acc[ptB / P], sdfB * sdfB);
                }
            }
        }
    }

    __syncthreads();
    if (tid < 2) {
        const float val = s_acc[tid];
        if (val != 0.0f) atomicAdd(&out[tid], val);
    }
}

extern "C" void kernel_launch(void* const* d_in, const int* in_sizes, int n_in,
                              void* d_out, int out_size)
{
    const float* points = (const float*)d_in[0];
    const float* v      = (const float*)d_in[1];
    const float* vn     = (const float*)d_in[2];
    const float* sr     = (const float*)d_in[3];
    float* out          = (float*)d_out;

    const int total_pts = in_sizes[0] / 3;          // N*P
    const int N         = out_size;                 // 2
    const int P         = total_pts / N;            // 100000
    const int K         = in_sizes[3] / total_pts;  // 60

    sdf_init_out<<<1, 32>>>(out, N);

    const int pairs  = (total_pts + 1) / 2;
    const int blocks = (pairs + WARPS_PER_BLOCK - 1) / WARPS_PER_BLOCK;

    if (K == 60) {
        sdf_kernel2<60><<<blocks, THREADS_PER_BLOCK>>>(points, v, vn, sr, out,
                                                       total_pts, P, K);
    } else {
        sdf_kernel2<0><<<blocks, THREADS_PER_BLOCK>>>(points, v, vn, sr, out,
                                                      total_pts, P, K);
    }
}